// round 3
// baseline (speedup 1.0000x reference)
#include <cuda_runtime.h>
#include <cuda_bf16.h>

// SimpleLSTM: B=64, T=2048, H=512.
// Persistent kernel: 128 CTAs = 4 batch-groups x 32 hidden-groups.
// W_hh slice resident in SMEM, c-state in registers, per-step cross-CTA h
// exchange through L2 with acquire/release flag sync. y head is a separate
// deterministic kernel over the full h history.

#define B_    64
#define T_    2048
#define H_    512
#define NCTA  128
#define NTHR  256
#define BS_   16    // batches per CTA
#define HS_   16    // hidden units per CTA
#define ROWS  64    // gate rows per CTA

// shared memory float offsets
#define OFF_W    0            // [512][64]     32768 floats (128 KB)
#define OFF_H    32768        // [512][16]      8192 floats (32 KB)
#define OFF_RED  40960        // [8][512] f2    8192 floats (32 KB)
#define OFF_WIH  49152        // [64]
#define OFF_BIAS 49216        // [64]
#define OFF_XT   49280        // [16]
#define SMEM_FLOATS 49312
#define SMEM_BYTES  (SMEM_FLOATS * 4)

// full h history, layout [t][unit][batch] (transposed for coalesced staging)
__device__ float    g_hall[(size_t)T_ * H_ * B_];
__device__ unsigned g_done[T_ + 1];

typedef unsigned long long ull;

__device__ __forceinline__ ull dup2(float x) {
    ull r; unsigned u = __float_as_uint(x);
    asm("mov.b64 %0, {%1, %1};" : "=l"(r) : "r"(u));
    return r;
}
__device__ __forceinline__ void fma2(ull& d, ull a, ull b) {
    asm("fma.rn.f32x2 %0, %1, %2, %0;" : "+l"(d) : "l"(a), "l"(b));
}
__device__ __forceinline__ float sigm(float x) {
    return __fdividef(1.0f, 1.0f + __expf(-x));
}
__device__ __forceinline__ float tanh_f(float x) {
    return __fdividef(2.0f, 1.0f + __expf(-2.0f * x)) - 1.0f;
}

__global__ void lstm_init_kernel() {
    int i = blockIdx.x * blockDim.x + threadIdx.x;
    if (i <= T_) g_done[i] = 0u;
}

__global__ void __launch_bounds__(NTHR, 1)
lstm_persistent_kernel(const float* __restrict__ x,
                       const float* __restrict__ W_ih,
                       const float* __restrict__ W_hh,
                       const float* __restrict__ b_ih,
                       const float* __restrict__ b_hh,
                       float* __restrict__ out) {
    extern __shared__ float sm[];
    float* sm_W    = sm + OFF_W;     // [k][64 rows]
    float* sm_H    = sm + OFF_H;     // [k][16 batches]
    ull*   sm_red  = (ull*)(sm + OFF_RED);  // [8 warps][512 outputs] (float2)
    float* sm_wih  = sm + OFF_WIH;
    float* sm_bias = sm + OFF_BIAS;
    float* sm_xt   = sm + OFF_XT;

    const int tid   = threadIdx.x;
    const int cta   = blockIdx.x;
    const int gh    = cta >> 2;           // hidden group 0..31
    const int gb    = cta & 3;            // batch group 0..3
    const int unit0 = gh * HS_;
    const int b0    = gb * BS_;

    const int w    = tid >> 5;            // warp 0..7 -> K slice [w*64, w*64+64)
    const int lane = tid & 31;
    const int rt   = lane & 15;           // rows rt*4 .. rt*4+3
    const int bg   = lane >> 4;           // batch-pairs bg*4 .. bg*4+3

    const int j  = tid & 15;              // elementwise: hidden unit local
    const int bb = tid >> 4;              // elementwise: batch local
    const int bp = bb >> 1;               // batch-pair
    const int bc = bb & 1;                // component within pair

    // ---- one-time preload: W slice (rows G = g*512 + unit0 + jj) ----
    for (int idx = tid; idx < ROWS * H_; idx += NTHR) {
        int r = idx >> 9;                 // local row 0..63 = g*16+jj
        int k = idx & 511;
        int G = ((r >> 4) << 9) + unit0 + (r & 15);
        sm_W[k * 64 + r] = W_hh[(size_t)G * H_ + k];
    }
    if (tid < ROWS) {
        int G = ((tid >> 4) << 9) + unit0 + (tid & 15);
        sm_wih[tid]  = W_ih[G];
        sm_bias[tid] = b_ih[G] + b_hh[G];
    }
    __syncthreads();

    float c_reg = 0.0f;

    const float* Wp = sm_W + (w * 64) * 64 + rt * 4;
    const float* Hp = sm_H + (w * 64) * 16 + bg * 8;

    for (int t = 0; t < T_; ++t) {
        // ---- wait until all CTAs published h_{t} ----
        if (t > 0 && tid == 0) {
            unsigned v;
            do {
                asm volatile("ld.acquire.gpu.global.u32 %0, [%1];"
                             : "=r"(v) : "l"(g_done + t) : "memory");
            } while (v < (unsigned)NCTA);
        }
        __syncthreads();

        // ---- stage x_t and h slice [512][16] ----
        if (tid < BS_) sm_xt[tid] = __ldg(&x[(b0 + tid) * T_ + t]);
        if (t == 0) {
            for (int i = tid; i < H_ * BS_; i += NTHR) sm_H[i] = 0.0f;
        } else {
            const float* hsrc = g_hall + (size_t)(t - 1) * H_ * B_;
#pragma unroll
            for (int it = 0; it < 8; ++it) {
                int id = tid + it * NTHR;        // 0..2047 float4 chunks
                int k  = id >> 2;
                int cc = id & 3;
                float4 v = __ldcg((const float4*)(hsrc + k * B_ + b0 + cc * 4));
                *(float4*)(sm_H + k * 16 + cc * 4) = v;
            }
        }
        __syncthreads();

        // ---- GEMM partials: 4 rows x 4 batch-pairs per lane, K-slice 64 ----
        ull acc[4][4];
#pragma unroll
        for (int r = 0; r < 4; ++r)
#pragma unroll
            for (int p = 0; p < 4; ++p) acc[r][p] = 0ull;

#pragma unroll 4
        for (int kk = 0; kk < 64; ++kk) {
            float4 wv = *(const float4*)(Wp + kk * 64);
            ulonglong2 hA = *(const ulonglong2*)(Hp + kk * 16);
            ulonglong2 hB = *(const ulonglong2*)(Hp + kk * 16 + 4);
            ull w0 = dup2(wv.x), w1 = dup2(wv.y), w2 = dup2(wv.z), w3 = dup2(wv.w);
            fma2(acc[0][0], w0, hA.x); fma2(acc[0][1], w0, hA.y);
            fma2(acc[0][2], w0, hB.x); fma2(acc[0][3], w0, hB.y);
            fma2(acc[1][0], w1, hA.x); fma2(acc[1][1], w1, hA.y);
            fma2(acc[1][2], w1, hB.x); fma2(acc[1][3], w1, hB.y);
            fma2(acc[2][0], w2, hA.x); fma2(acc[2][1], w2, hA.y);
            fma2(acc[2][2], w2, hB.x); fma2(acc[2][3], w2, hB.y);
            fma2(acc[3][0], w3, hA.x); fma2(acc[3][1], w3, hA.y);
            fma2(acc[3][2], w3, hB.x); fma2(acc[3][3], w3, hB.y);
        }

#pragma unroll
        for (int r = 0; r < 4; ++r)
#pragma unroll
            for (int p = 0; p < 4; ++p) {
                int row = rt * 4 + r;
                int pp  = bg * 4 + p;
                sm_red[w * 512 + row * 8 + pp] = acc[r][p];
            }
        __syncthreads();

        // ---- reduce 8 K-slices + cell update (thread owns (bb, j)) ----
        float gate[4];
        const float* redf = sm + OFF_RED;
#pragma unroll
        for (int g = 0; g < 4; ++g) {
            int row = g * 16 + j;
            const float* rp = redf + (row * 8 + bp) * 2 + bc;
            float s = 0.0f;
#pragma unroll
            for (int ww = 0; ww < 8; ++ww) s += rp[ww * 1024];
            gate[g] = s + sm_xt[bb] * sm_wih[row] + sm_bias[row];
        }
        float ig = sigm(gate[0]);
        float fg = sigm(gate[1]);
        float gg = tanh_f(gate[2]);
        float og = sigm(gate[3]);
        c_reg = fg * c_reg + ig * gg;
        float h = og * tanh_f(c_reg);

        __stcg(&g_hall[((size_t)t * H_ + unit0 + j) * B_ + b0 + bb], h);
        if (t == T_ - 1) {
            out[B_ * T_ + (b0 + bb) * H_ + unit0 + j]            = h;      // h_n
            out[B_ * T_ + B_ * H_ + (b0 + bb) * H_ + unit0 + j]  = c_reg;  // c_n
        }

        __syncthreads();
        if (tid == 0) {
            __threadfence();
            atomicAdd(&g_done[t + 1], 1u);
        }
    }
}

// y[b,t] = b_fc + sum_u h[t][u][b] * W_fc[u]
__global__ void fc_kernel(const float* __restrict__ W_fc,
                          const float* __restrict__ b_fc,
                          float* __restrict__ out) {
    int i = blockIdx.x * blockDim.x + threadIdx.x;   // 0..131071
    int b = i & (B_ - 1);
    int t = i >> 6;
    const float* hp = g_hall + (size_t)t * H_ * B_ + b;
    float s = 0.0f;
#pragma unroll 8
    for (int u = 0; u < H_; ++u) s += hp[u * B_] * __ldg(&W_fc[u]);
    out[b * T_ + t] = s + __ldg(&b_fc[0]);
}

extern "C" void kernel_launch(void* const* d_in, const int* in_sizes, int n_in,
                              void* d_out, int out_size) {
    (void)in_sizes; (void)n_in; (void)out_size;
    const float* x    = (const float*)d_in[0];
    const float* W_ih = (const float*)d_in[1];
    const float* W_hh = (const float*)d_in[2];
    const float* b_ih = (const float*)d_in[3];
    const float* b_hh = (const float*)d_in[4];
    const float* W_fc = (const float*)d_in[5];
    const float* b_fc = (const float*)d_in[6];
    float* out = (float*)d_out;

    static bool attr_set = false;
    if (!attr_set) {
        cudaFuncSetAttribute(lstm_persistent_kernel,
                             cudaFuncAttributeMaxDynamicSharedMemorySize,
                             SMEM_BYTES);
        attr_set = true;
    }

    lstm_init_kernel<<<(T_ + 1 + 255) / 256, 256>>>();
    lstm_persistent_kernel<<<NCTA, NTHR, SMEM_BYTES>>>(x, W_ih, W_hh, b_ih, b_hh, out);
    fc_kernel<<<(B_ * T_) / 256, 256>>>(W_fc, b_fc, out);
}

// round 5
// speedup vs baseline: 1.4007x; 1.4007x over previous
#include <cuda_runtime.h>
#include <cuda_bf16.h>

// SimpleLSTM: B=64, T=2048, H=512.
// Persistent kernel: 128 CTAs = 4 batch-groups x 32 hidden-groups.
// W_hh slice resident in SMEM (row-permuted for conflict-free reduction),
// c-state in registers, per-step cross-CTA h exchange through L2 with
// per-batch-group acquire/release flag sync. y head = separate kernel.

#define B_    64
#define T_    2048
#define H_    512
#define NCTA  128
#define NTHR  256
#define BS_   16    // batches per CTA
#define HS_   16    // hidden units per CTA
#define ROWS  64    // gate rows per CTA

// shared memory float offsets
#define OFF_W    0            // [512][64]     32768 floats (128 KB), row-permuted
#define OFF_H    32768        // [512][16]      8192 floats (32 KB)
#define OFF_RED  40960        // [8][8][64] f2  8192 floats (32 KB)
#define OFF_WIH  49152        // [64]
#define OFF_BIAS 49216        // [64]
#define OFF_XT   49280        // [16]
#define SMEM_FLOATS 49312
#define SMEM_BYTES  (SMEM_FLOATS * 4)

#define FLAGSTR 32            // 128B stride between counters

// full h history, layout [t][unit][batch] (transposed for coalesced staging)
__device__ float    g_hall[(size_t)T_ * H_ * B_];
__device__ unsigned g_done[(T_ + 1) * 4 * FLAGSTR];

typedef unsigned long long ull;

__device__ __forceinline__ ull dup2(float x) {
    ull r; unsigned u = __float_as_uint(x);
    asm("mov.b64 %0, {%1, %1};" : "=l"(r) : "r"(u));
    return r;
}
__device__ __forceinline__ void fma2(ull& d, ull a, ull b) {
    asm("fma.rn.f32x2 %0, %1, %2, %0;" : "+l"(d) : "l"(a), "l"(b));
}
__device__ __forceinline__ float sigm(float x) {
    return __fdividef(1.0f, 1.0f + __expf(-x));
}
__device__ __forceinline__ float tanh_f(float x) {
    return __fdividef(2.0f, 1.0f + __expf(-2.0f * x)) - 1.0f;
}

__global__ void lstm_init_kernel() {
    int i = blockIdx.x * blockDim.x + threadIdx.x;
    if (i < (T_ + 1) * 4 * FLAGSTR) g_done[i] = 0u;
}

__global__ void __launch_bounds__(NTHR, 1)
lstm_persistent_kernel(const float* __restrict__ x,
                       const float* __restrict__ W_ih,
                       const float* __restrict__ W_hh,
                       const float* __restrict__ b_ih,
                       const float* __restrict__ b_hh,
                       float* __restrict__ out) {
    extern __shared__ float sm[];
    float* sm_W    = sm + OFF_W;             // [k][64 slots], permuted rows
    float* sm_H    = sm + OFF_H;             // [k][16 batches]
    ull*   sm_red  = (ull*)(sm + OFF_RED);   // [8 warps][8 pp][64 rows]
    float* sm_redf = sm + OFF_RED;
    float* sm_wih  = sm + OFF_WIH;
    float* sm_bias = sm + OFF_BIAS;
    float* sm_xt   = sm + OFF_XT;

    const int tid   = threadIdx.x;
    const int cta   = blockIdx.x;
    const int gh    = cta >> 2;           // hidden group 0..31
    const int gb    = cta & 3;            // batch group 0..3
    const int unit0 = gh * HS_;
    const int b0    = gb * BS_;

    const int w    = tid >> 5;            // warp 0..7 -> K slice [w*64, w*64+64)
    const int lane = tid & 31;
    const int rt   = lane & 15;           // slot group: rows {rt,16+rt,32+rt,48+rt}
    const int bg   = lane >> 4;           // batch-pairs bg*4 .. bg*4+3

    const int j  = tid & 15;              // elementwise: hidden unit local
    const int bb = tid >> 4;              // elementwise: batch local
    const int bp = bb >> 1;               // batch-pair
    const int bc = bb & 1;                // component within pair

    // ---- one-time preload: W slice, slot s = rt*4+r holds local row r*16+rt ----
    for (int idx = tid; idx < ROWS * H_; idx += NTHR) {
        int s = idx >> 9;                 // slot 0..63
        int k = idx & 511;
        int rl = ((s & 3) << 4) + (s >> 2);       // permuted local row
        int G = ((rl >> 4) << 9) + unit0 + (rl & 15);
        sm_W[k * 64 + s] = W_hh[(size_t)G * H_ + k];
    }
    if (tid < ROWS) {
        int G = ((tid >> 4) << 9) + unit0 + (tid & 15);
        sm_wih[tid]  = W_ih[G];
        sm_bias[tid] = b_ih[G] + b_hh[G];
    }
    __syncthreads();

    float c_reg = 0.0f;

    const float* Wp = sm_W + (w * 64) * 64 + rt * 4;
    const float* Hp = sm_H + (w * 64) * 16 + bg * 8;

    for (int t = 0; t < T_; ++t) {
        // ---- wait until the 32 CTAs of this batch-group published h_{t-1} ----
        if (t > 0 && tid == 0) {
            const unsigned* f = g_done + ((t << 2) + gb) * FLAGSTR;
            unsigned v;
            do {
                asm volatile("ld.acquire.gpu.global.u32 %0, [%1];"
                             : "=r"(v) : "l"(f) : "memory");
            } while (v < 32u);
        }
        __syncthreads();

        // ---- stage x_t and h slice [512][16] ----
        if (tid < BS_) sm_xt[tid] = __ldg(&x[(b0 + tid) * T_ + t]);
        if (t == 0) {
            for (int i = tid; i < H_ * BS_; i += NTHR) sm_H[i] = 0.0f;
        } else {
            const float* hsrc = g_hall + (size_t)(t - 1) * H_ * B_;
#pragma unroll
            for (int it = 0; it < 8; ++it) {
                int id = tid + it * NTHR;        // 0..2047 float4 chunks
                int k  = id >> 2;
                int cc = id & 3;
                float4 v = __ldcg((const float4*)(hsrc + k * B_ + b0 + cc * 4));
                *(float4*)(sm_H + k * 16 + cc * 4) = v;
            }
        }
        __syncthreads();

        // ---- GEMM partials: rows {r*16+rt}, 4 batch-pairs per lane, K=64 ----
        ull acc[4][4];
#pragma unroll
        for (int r = 0; r < 4; ++r)
#pragma unroll
            for (int p = 0; p < 4; ++p) acc[r][p] = 0ull;

#pragma unroll 4
        for (int kk = 0; kk < 64; ++kk) {
            float4 wv = *(const float4*)(Wp + kk * 64);
            ulonglong2 hA = *(const ulonglong2*)(Hp + kk * 16);
            ulonglong2 hB = *(const ulonglong2*)(Hp + kk * 16 + 4);
            ull w0 = dup2(wv.x), w1 = dup2(wv.y), w2 = dup2(wv.z), w3 = dup2(wv.w);
            fma2(acc[0][0], w0, hA.x); fma2(acc[0][1], w0, hA.y);
            fma2(acc[0][2], w0, hB.x); fma2(acc[0][3], w0, hB.y);
            fma2(acc[1][0], w1, hA.x); fma2(acc[1][1], w1, hA.y);
            fma2(acc[1][2], w1, hB.x); fma2(acc[1][3], w1, hB.y);
            fma2(acc[2][0], w2, hA.x); fma2(acc[2][1], w2, hA.y);
            fma2(acc[2][2], w2, hB.x); fma2(acc[2][3], w2, hB.y);
            fma2(acc[3][0], w3, hA.x); fma2(acc[3][1], w3, hA.y);
            fma2(acc[3][2], w3, hB.x); fma2(acc[3][3], w3, hB.y);
        }

        // store: row stride 1 across lanes -> conflict-free
#pragma unroll
        for (int r = 0; r < 4; ++r)
#pragma unroll
            for (int p = 0; p < 4; ++p) {
                int row = (r << 4) + rt;          // true local row
                int pp  = (bg << 2) + p;
                sm_red[w * 512 + pp * 64 + row] = acc[r][p];
            }
        __syncthreads();

        // ---- reduce 8 K-slices + cell update (thread owns (bb, j)) ----
        float gate[4];
#pragma unroll
        for (int g = 0; g < 4; ++g) {
            int row = (g << 4) + j;
            const float* rp = sm_redf + bp * 128 + row * 2 + bc;
            float s = 0.0f;
#pragma unroll
            for (int ww = 0; ww < 8; ++ww) s += rp[ww * 1024];
            gate[g] = s + sm_xt[bb] * sm_wih[row] + sm_bias[row];
        }
        float ig = sigm(gate[0]);
        float fg = sigm(gate[1]);
        float gg = tanh_f(gate[2]);
        float og = sigm(gate[3]);
        c_reg = fg * c_reg + ig * gg;
        float h = og * tanh_f(c_reg);

        __stcg(&g_hall[((size_t)t * H_ + unit0 + j) * B_ + b0 + bb], h);
        if (t == T_ - 1) {
            out[B_ * T_ + (b0 + bb) * H_ + unit0 + j]            = h;      // h_n
            out[B_ * T_ + B_ * H_ + (b0 + bb) * H_ + unit0 + j]  = c_reg;  // c_n
        }

        __syncthreads();
        if (tid == 0) {
            __threadfence();
            unsigned* f = g_done + (((t + 1) << 2) + gb) * FLAGSTR;
            asm volatile("red.relaxed.gpu.global.add.u32 [%0], %1;"
                         :: "l"(f), "r"(1u) : "memory");
        }
    }
}

// y[b,t] = b_fc + sum_u h[t][u][b] * W_fc[u]
__global__ void fc_kernel(const float* __restrict__ W_fc,
                          const float* __restrict__ b_fc,
                          float* __restrict__ out) {
    int i = blockIdx.x * blockDim.x + threadIdx.x;   // 0..131071
    int b = i & (B_ - 1);
    int t = i >> 6;
    const float* hp = g_hall + (size_t)t * H_ * B_ + b;
    float s = 0.0f;
#pragma unroll 8
    for (int u = 0; u < H_; ++u) s += hp[u * B_] * __ldg(&W_fc[u]);
    out[b * T_ + t] = s + __ldg(&b_fc[0]);
}

extern "C" void kernel_launch(void* const* d_in, const int* in_sizes, int n_in,
                              void* d_out, int out_size) {
    (void)in_sizes; (void)n_in; (void)out_size;
    const float* x    = (const float*)d_in[0];
    const float* W_ih = (const float*)d_in[1];
    const float* W_hh = (const float*)d_in[2];
    const float* b_ih = (const float*)d_in[3];
    const float* b_hh = (const float*)d_in[4];
    const float* W_fc = (const float*)d_in[5];
    const float* b_fc = (const float*)d_in[6];
    float* out = (float*)d_out;

    static bool attr_set = false;
    if (!attr_set) {
        cudaFuncSetAttribute(lstm_persistent_kernel,
                             cudaFuncAttributeMaxDynamicSharedMemorySize,
                             SMEM_BYTES);
        attr_set = true;
    }

    lstm_init_kernel<<<((T_ + 1) * 4 * FLAGSTR + 255) / 256, 256>>>();
    lstm_persistent_kernel<<<NCTA, NTHR, SMEM_BYTES>>>(x, W_ih, W_hh, b_ih, b_hh, out);
    fc_kernel<<<(B_ * T_) / 256, 256>>>(W_fc, b_fc, out);
}